// round 17
// baseline (speedup 1.0000x reference)
#include <cuda_runtime.h>
#include <math.h>

typedef unsigned long long u64;

// Round 17: R16 base + balanced phase A for g<10 (B-half xi channels split
// 3 pairs per warp-half so no warps idle through the 64-k loop).

#define HALO   240     // 20 x 12
#define SM_SX     0        // 64*240 = 15360
#define SM_SPN    15360    // 480
#define SM_XC     15840    // 5760
#define SM_D3B    21600    // 8*128 = 1024
#define SM_D1     22624    // 8*128 = 1024
#define SM_WT     23648    // 1536
#define SM_GDW31  25184    // 8 cc * 56
#define SM_GDW3B  25632    // 96
#define SM_GWOUT  25728    // 256
#define SM_BDW1   25984    // 128
#define SM_BDW3A  26112    // 128
#define SM_BDW3B  26240    // 128
#define SM_BOUT   26368    // 64
#define SM_WPN    26432    // 256
#define SM_BPN    26688    // 128
#define SM_BIN    26816    // 256
#define SM_TOTAL  27072    // 108288 bytes -> 2 blocks/SM

__device__ __forceinline__ u64 pk2(float lo, float hi) {
    u64 r; asm("mov.b64 %0,{%1,%2};" : "=l"(r) : "f"(lo), "f"(hi)); return r;
}
__device__ __forceinline__ void upk2(u64 v, float& lo, float& hi) {
    asm("mov.b64 {%0,%1},%2;" : "=f"(lo), "=f"(hi) : "l"(v));
}
__device__ __forceinline__ void fma2(u64& d, u64 a, u64 b) {
    asm("fma.rn.f32x2 %0,%1,%2,%0;" : "+l"(d) : "l"(a), "l"(b));
}
__device__ __forceinline__ u64 lds64(const float* p) { return *(const u64*)p; }

__device__ __forceinline__ float gelu_exact(float v) {
    return 0.5f * v * (1.0f + erff(v * 0.70710678118654752f));
}

// B-half xi, 3 channel-pairs starting at pair PB (slots 12+2*PB..17+2*PB).
template<int PB>
__device__ __forceinline__ void phaseA_B3(float* sm, int g, int p0,
                                          float m0, float m1)
{
    u64 a0[3], a1[3];
#pragma unroll
    for (int j = 0; j < 3; ++j) {
        u64 bp = lds64(sm + SM_BIN + 64 + 12 * g + 2 * (PB + j));
        a0[j] = bp; a1[j] = bp;
    }
#pragma unroll 4
    for (int k = 0; k < 64; ++k) {
        float2 s = *(const float2*)(sm + SM_SX + k * 240 + p0);
        u64 s0 = pk2(s.x, s.x);
        u64 s1 = pk2(s.y, s.y);
        const float* wt = sm + SM_WT + k * 24 + 2 * PB;
        u64 w0 = lds64(wt), w1 = lds64(wt + 2), w2 = lds64(wt + 4);
        fma2(a0[0], w0, s0); fma2(a1[0], w0, s1);
        fma2(a0[1], w1, s0); fma2(a1[1], w1, s1);
        fma2(a0[2], w2, s0); fma2(a1[2], w2, s1);
    }
#pragma unroll
    for (int j = 0; j < 3; ++j) {
        float lo0, hi0, lo1, hi1;
        upk2(a0[j], lo0, hi0);
        upk2(a1[j], lo1, hi1);
        float* c0 = sm + SM_XC + (12 + 2 * (PB + j)) * 240 + p0;
        float* c1 = sm + SM_XC + (13 + 2 * (PB + j)) * 240 + p0;
        c0[0] = lo0 * m0; c0[1] = lo1 * m1;
        c1[0] = hi0 * m0; c1[1] = hi1 * m1;
    }
}

// Full B-half (6 pairs) — used for g >= 10 where gh=1 handles A-half xi.
__device__ __forceinline__ void phaseA_B6(float* sm, int g, int p0,
                                          float m0, float m1)
{
    u64 a0[6], a1[6];
#pragma unroll
    for (int j = 0; j < 6; ++j) {
        u64 bp = lds64(sm + SM_BIN + 64 + 12 * g + 2 * j);
        a0[j] = bp; a1[j] = bp;
    }
#pragma unroll 4
    for (int k = 0; k < 64; ++k) {
        float2 s = *(const float2*)(sm + SM_SX + k * 240 + p0);
        u64 s0 = pk2(s.x, s.x);
        u64 s1 = pk2(s.y, s.y);
        const float* wt = sm + SM_WT + k * 24;
        ulonglong2 w01 = *(const ulonglong2*)(wt);
        ulonglong2 w23 = *(const ulonglong2*)(wt + 4);
        ulonglong2 w45 = *(const ulonglong2*)(wt + 8);
        fma2(a0[0], w01.x, s0); fma2(a1[0], w01.x, s1);
        fma2(a0[1], w01.y, s0); fma2(a1[1], w01.y, s1);
        fma2(a0[2], w23.x, s0); fma2(a1[2], w23.x, s1);
        fma2(a0[3], w23.y, s0); fma2(a1[3], w23.y, s1);
        fma2(a0[4], w45.x, s0); fma2(a1[4], w45.x, s1);
        fma2(a0[5], w45.y, s0); fma2(a1[5], w45.y, s1);
    }
#pragma unroll
    for (int j = 0; j < 6; ++j) {
        float lo0, hi0, lo1, hi1;
        upk2(a0[j], lo0, hi0);
        upk2(a1[j], lo1, hi1);
        float* c0 = sm + SM_XC + (12 + 2 * j) * 240 + p0;
        float* c1 = sm + SM_XC + (13 + 2 * j) * 240 + p0;
        c0[0] = lo0 * m0; c0[1] = lo1 * m1;
        c1[0] = hi0 * m0; c1[1] = hi1 * m1;
    }
}

// pn channels for A-half slots [s0, s1).
__device__ __forceinline__ void phaseA_pn(float* sm, int g, int p0,
                                          float m0, float m1,
                                          float pn00, float pn01,
                                          float pn10, float pn11,
                                          int s0i, int s1i)
{
    for (int s = s0i; s < s1i; ++s) {
        int c = 12 * g + s;
        float w0 = sm[SM_WPN + 2 * c], w1 = sm[SM_WPN + 2 * c + 1];
        float bb = sm[SM_BPN + c];
        float v0 = fmaf(w0, pn00, fmaf(w1, pn10, bb));
        float v1 = fmaf(w0, pn01, fmaf(w1, pn11, bb));
        float* cp = sm + SM_XC + s * 240 + p0;
        cp[0] = v0 * m0;
        cp[1] = v1 * m1;
    }
}

// A-half xi for g>=10. NP = xi channel pairs {2, 6}.
template<int NP>
__device__ __forceinline__ void phaseA_Axi(float* sm, int g, int p0,
                                           float m0, float m1)
{
    u64 a0[NP], a1[NP];
    const int base = (NP == 2) ? 0 : (12 * g - 128);
#pragma unroll
    for (int j = 0; j < NP; ++j) {
        u64 bp = lds64(sm + SM_BIN + base + 2 * j);
        a0[j] = bp; a1[j] = bp;
    }
#pragma unroll 4
    for (int k = 0; k < 64; ++k) {
        float2 s = *(const float2*)(sm + SM_SX + k * 240 + p0);
        u64 s0 = pk2(s.x, s.x);
        u64 s1 = pk2(s.y, s.y);
        const float* wt = sm + SM_WT + k * 24 + 12;
#pragma unroll
        for (int j = 0; j < NP; ++j) {
            u64 w = lds64(wt + 2 * j);
            fma2(a0[j], w, s0);
            fma2(a1[j], w, s1);
        }
    }
    const int sb = (NP == 2) ? 8 : 0;
#pragma unroll
    for (int j = 0; j < NP; ++j) {
        float lo0, hi0, lo1, hi1;
        upk2(a0[j], lo0, hi0);
        upk2(a1[j], lo1, hi1);
        float* c0 = sm + SM_XC + (sb + 2 * j) * 240 + p0;
        float* c1 = sm + SM_XC + (sb + 2 * j + 1) * 240 + p0;
        c0[0] = lo0 * m0; c0[1] = lo1 * m1;
        c1[0] = hi0 * m0; c1[1] = hi1 * m1;
    }
}

__global__ void __launch_bounds__(256, 2)
ffn_fused_kernel(const float* __restrict__ x,
                 const float* __restrict__ pneff,
                 const float* __restrict__ w_in,  const float* __restrict__ b_in,
                 const float* __restrict__ w_pn,  const float* __restrict__ b_pn,
                 const float* __restrict__ w_dw1, const float* __restrict__ b_dw1,
                 const float* __restrict__ w_dw3a,const float* __restrict__ b_dw3a,
                 const float* __restrict__ w_dw3b,const float* __restrict__ b_dw3b,
                 const float* __restrict__ w_out, const float* __restrict__ b_out,
                 float* __restrict__ out)
{
    extern __shared__ float sm[];
    const int tid = threadIdx.x;
    const int bx0 = blockIdx.x * 16;
    const int by0 = blockIdx.y * 8;
    const int b   = blockIdx.z;

    if (tid < 128) {
        sm[SM_BDW1 + tid]  = b_dw1[tid];
        sm[SM_BDW3A + tid] = b_dw3a[tid];
        sm[SM_BDW3B + tid] = b_dw3b[tid];
        sm[SM_BPN + tid]   = b_pn[tid];
    }
    if (tid < 64) sm[SM_BOUT + tid] = b_out[tid];
    sm[SM_WPN + tid] = w_pn[tid];
    sm[SM_BIN + tid] = b_in[tid];

    {
        const float* xb = x + (size_t)b * 64 * 65536;
        for (int v = tid; v < 64 * HALO; v += 256) {
            int c = v / HALO, p = v - c * HALO;
            int ry = p / 20, rx = p - ry * 20;
            int gy = by0 + ry - 2, gx = bx0 + rx - 2;
            float vv = 0.0f;
            if ((unsigned)gy < 256u && (unsigned)gx < 256u)
                vv = xb[(size_t)c * 65536 + gy * 256 + gx];
            sm[SM_SX + c * HALO + p] = vv;
        }
        const float* pnb = pneff + (size_t)b * 2 * 65536;
        for (int v = tid; v < 2 * HALO; v += 256) {
            int c = v / HALO, p = v - c * HALO;
            int ry = p / 20, rx = p - ry * 20;
            int gy = by0 + ry - 2, gx = bx0 + rx - 2;
            float vv = 0.0f;
            if ((unsigned)gy < 256u && (unsigned)gx < 256u)
                vv = pnb[(size_t)c * 65536 + gy * 256 + gx];
            sm[SM_SPN + c * HALO + p] = vv;
        }
    }
    __syncthreads();

    const int tA  = tid & 127;
    const int gh  = tid >> 7;
    const bool doA = (tA < 120);
    const int p0  = doA ? (2 * tA) : 0;
    float m0, m1;
    {
        int ry = p0 / 20, rx = p0 - ry * 20;
        m0 = ((unsigned)(by0 + ry - 2) < 256u && (unsigned)(bx0 + rx - 2) < 256u) ? 1.f : 0.f;
        int p1 = p0 + 1;
        int ry1 = p1 / 20, rx1 = p1 - ry1 * 20;
        m1 = ((unsigned)(by0 + ry1 - 2) < 256u && (unsigned)(bx0 + rx1 - 2) < 256u) ? 1.f : 0.f;
    }
    const float pn00 = sm[SM_SPN + p0],        pn01 = sm[SM_SPN + p0 + 1];
    const float pn10 = sm[SM_SPN + HALO + p0], pn11 = sm[SM_SPN + HALO + p0 + 1];

    const int tyl  = tA >> 4;
    const int tx   = tA & 15;
    const int warp = tid >> 5;
    const int lane = tid & 31;

    u64 acc[16];
#pragma unroll
    for (int i = 0; i < 16; ++i) acc[i] = 0ULL;

    for (int g = 0; g < 16; ++g) {
        // ---- stage per-group weights ----
        {
            const int nw = (g < 10) ? 768 : (g == 10 ? 1024 : 1536);
            const int ncol = nw / 64;
            for (int v = tid; v < nw; v += 256) {
                int k = v / ncol, j = v - k * ncol;
                int xi = (j < 12) ? (64 + 12 * g + j)
                                  : ((g == 10) ? (j - 12) : (12 * g - 128 + j - 12));
                sm[SM_WT + k * 24 + j] = w_in[xi * 64 + k];
            }
            for (int v = tid; v < 216; v += 256) {
                int cc = v / 27, t = v - cc * 27;
                int ch = 4 * g + (cc >> 1) + (cc & 1) * 64;
                sm[SM_GDW31 + cc * 56 + 2 * t]     = w_dw3a[ch * 27 + t];
                sm[SM_GDW31 + cc * 56 + 2 * t + 1] = w_dw1[ch * 27 + t];
            }
            if (tid < 72) {
                int cc = tid / 9, t = tid - cc * 9;
                int ch = 4 * g + (cc >> 1) + (cc & 1) * 64;
                sm[SM_GDW3B + cc * 12 + t] = w_dw3b[ch * 9 + t];
            }
            {
                int cpl = tid >> 6, o = tid & 63;
                sm[SM_GWOUT + tid] = w_out[o * 64 + 4 * g + cpl];
            }
        }
        __syncthreads();   // weights ready

        // ---- Phase A (balanced split) ----
        if (doA) {
            if (g < 10) {
                if (gh == 0) {
                    phaseA_B3<0>(sm, g, p0, m0, m1);
                } else {
                    phaseA_pn(sm, g, p0, m0, m1, pn00, pn01, pn10, pn11, 0, 12);
                    phaseA_B3<3>(sm, g, p0, m0, m1);
                }
            } else if (g == 10) {
                if (gh == 0) {
                    phaseA_B6(sm, g, p0, m0, m1);
                } else {
                    phaseA_pn(sm, g, p0, m0, m1, pn00, pn01, pn10, pn11, 0, 8);
                    phaseA_Axi<2>(sm, g, p0, m0, m1);
                }
            } else {
                if (gh == 0) phaseA_B6(sm, g, p0, m0, m1);
                else         phaseA_Axi<6>(sm, g, p0, m0, m1);
            }
        }
        __syncthreads();   // XC ready

        // ---- Merged B1+B2 ({d3,d1} paired) + in-register B3 ----
        {
            const int cpl = warp >> 1, h = warp & 1;
            const int cc = cpl * 2 + h;
            const int cp = 4 * g + cpl;
            const bool ld = (lane < 20);

            u64 d[10];
            {
                float b3 = sm[SM_BDW3A + cp + h * 64];
                float b1 = sm[SM_BDW1 + cp + h * 64];
                u64 bp = pk2(b3, b1);
#pragma unroll
                for (int qy = 0; qy < 10; ++qy) d[qy] = bp;
            }

#pragma unroll
            for (int j = 0; j < 3; ++j) {
                u64 w[9];
#pragma unroll
                for (int t = 0; t < 9; ++t)
                    w[t] = lds64(sm + SM_GDW31 + cc * 56 + 2 * (j * 9 + t));
                const float* xc = sm + SM_XC + (h * 12 + 3 * cpl + j) * 240;
                float v0, q0, r0, v1, q1, r1, v2, q2, r2;
                {
                    float a = ld ? xc[lane] : 0.0f;
                    v0 = a;
                    q0 = __shfl_down_sync(0xffffffffu, a, 1);
                    r0 = __shfl_down_sync(0xffffffffu, a, 2);
                    float bva = ld ? xc[20 + lane] : 0.0f;
                    v1 = bva;
                    q1 = __shfl_down_sync(0xffffffffu, bva, 1);
                    r1 = __shfl_down_sync(0xffffffffu, bva, 2);
                }
#pragma unroll
                for (int qy = 0; qy < 10; ++qy) {
                    float c = ld ? xc[(qy + 2) * 20 + lane] : 0.0f;
                    v2 = c;
                    q2 = __shfl_down_sync(0xffffffffu, c, 1);
                    r2 = __shfl_down_sync(0xffffffffu, c, 2);

                    u64 dd = d[qy];
                    fma2(dd, w[0], pk2(v0, v0));
                    fma2(dd, w[1], pk2(q0, q0));
                    fma2(dd, w[2], pk2(r0, r0));
                    fma2(dd, w[3], pk2(v1, v1));
                    fma2(dd, w[4], pk2(q1, q1));
                    fma2(dd, w[5], pk2(r1, r1));
                    fma2(dd, w[6], pk2(v2, v2));
                    fma2(dd, w[7], pk2(q2, q2));
                    fma2(dd, w[8], pk2(r2, r2));
                    d[qy] = dd;

                    v0 = v1; q0 = q1; r0 = r1;
                    v1 = v2; q1 = q2; r1 = r2;
                }
            }

            // finalize: store d1, mask d3 in registers
            float e[10];
            {
                const bool stv = (lane < 18);
                const bool st1 = (lane >= 1 && lane <= 16);
                const int gxc  = bx0 + lane - 1;
                const bool colOK = stv && ((unsigned)gxc < 256u);
                float* dst1 = sm + SM_D1 + cc * 128;
#pragma unroll
                for (int qy = 0; qy < 10; ++qy) {
                    float d3, d1;
                    upk2(d[qy], d3, d1);
                    int gy = by0 + qy - 1;
                    bool ok = colOK && ((unsigned)gy < 256u);
                    e[qy] = ok ? d3 : 0.0f;
                    if (qy >= 1 && qy <= 8 && st1)
                        dst1[(qy - 1) * 16 + lane - 1] = d1;
                }
            }
            // B3 in-register
            {
                float e1[10], e2[10];
#pragma unroll
                for (int qy = 0; qy < 10; ++qy) {
                    e1[qy] = __shfl_down_sync(0xffffffffu, e[qy], 1);
                    e2[qy] = __shfl_down_sync(0xffffffffu, e[qy], 2);
                }
                float w3b[9];
#pragma unroll
                for (int t = 0; t < 9; ++t)
                    w3b[t] = sm[SM_GDW3B + cc * 12 + t];
                const float bb3 = sm[SM_BDW3B + cp + h * 64];
                float* dstb = sm + SM_D3B + cc * 128;
#pragma unroll
                for (int r = 0; r < 8; ++r) {
                    float o = bb3;
#pragma unroll
                    for (int ky = 0; ky < 3; ++ky) {
                        o = fmaf(w3b[3 * ky],     e[r + ky],  o);
                        o = fmaf(w3b[3 * ky + 1], e1[r + ky], o);
                        o = fmaf(w3b[3 * ky + 2], e2[r + ky], o);
                    }
                    if (lane < 16) dstb[r * 16 + lane] = o;
                }
            }
        }
        __syncthreads();   // D1 + D3B ready

        if (gh == 0) {
            // ---- gating + packed proj (o 0..31) from D1 ----
#pragma unroll
            for (int cpl = 0; cpl < 4; ++cpl) {
                float d1a = sm[SM_D1 + (cpl * 2 + 0) * 128 + tA];
                float d1b = sm[SM_D1 + (cpl * 2 + 1) * 128 + tA];
                float g1 = gelu_exact(d1a) * d1b;
                u64 g1p = pk2(g1, g1);
                const ulonglong2* wo = (const ulonglong2*)(sm + SM_GWOUT + cpl * 64);
#pragma unroll
                for (int mm = 0; mm < 8; ++mm) {
                    ulonglong2 w2 = wo[mm];
                    fma2(acc[2 * mm], w2.x, g1p);
                    fma2(acc[2 * mm + 1], w2.y, g1p);
                }
            }
        } else {
            // ---- gating + packed proj (o 32..63) from D3B ----
#pragma unroll
            for (int cpl = 0; cpl < 4; ++cpl) {
                float dA = sm[SM_D3B + (cpl * 2 + 0) * 128 + tA];
                float dB = sm[SM_D3B + (cpl * 2 + 1) * 128 + tA];
                float g2 = gelu_exact(dA) * dB;
                u64 g2p = pk2(g2, g2);
                const ulonglong2* wo = (const ulonglong2*)(sm + SM_GWOUT + cpl * 64 + 32);
#pragma unroll
                for (int mm = 0; mm < 8; ++mm) {
                    ulonglong2 w2 = wo[mm];
                    fma2(acc[2 * mm], w2.x, g2p);
                    fma2(acc[2 * mm + 1], w2.y, g2p);
                }
            }
        }
        __syncthreads();   // protect WT/GDW*/XC/D1/D3B before next staging
    }

    float* ob = out + (size_t)b * 64 * 65536 + (size_t)(by0 + tyl) * 256 + (bx0 + tx);
    const int o0 = gh * 32;
#pragma unroll
    for (int mm = 0; mm < 16; ++mm) {
        float lo, hi;
        upk2(acc[mm], lo, hi);
        ob[(size_t)(o0 + 2 * mm) * 65536]     = lo + sm[SM_BOUT + o0 + 2 * mm];
        ob[(size_t)(o0 + 2 * mm + 1) * 65536] = hi + sm[SM_BOUT + o0 + 2 * mm + 1];
    }
}

extern "C" void kernel_launch(void* const* d_in, const int* in_sizes, int n_in,
                              void* d_out, int out_size)
{
    (void)in_sizes; (void)n_in; (void)out_size;
    const float* x      = (const float*)d_in[0];
    const float* pneff  = (const float*)d_in[1];
    const float* w_in   = (const float*)d_in[2];
    const float* b_in   = (const float*)d_in[3];
    const float* w_pn   = (const float*)d_in[4];
    const float* b_pn   = (const float*)d_in[5];
    const float* w_dw1  = (const float*)d_in[6];
    const float* b_dw1  = (const float*)d_in[7];
    const float* w_dw3a = (const float*)d_in[8];
    const float* b_dw3a = (const float*)d_in[9];
    const float* w_dw3b = (const float*)d_in[10];
    const float* b_dw3b = (const float*)d_in[11];
    const float* w_out  = (const float*)d_in[12];
    const float* b_out  = (const float*)d_in[13];
    float* out = (float*)d_out;

    const size_t smem_bytes = SM_TOTAL * sizeof(float);
    cudaFuncSetAttribute(ffn_fused_kernel,
                         cudaFuncAttributeMaxDynamicSharedMemorySize,
                         (int)smem_bytes);
    dim3 grid(16, 32, 4);
    ffn_fused_kernel<<<grid, 256, smem_bytes>>>(
        x, pneff, w_in, b_in, w_pn, b_pn, w_dw1, b_dw1,
        w_dw3a, b_dw3a, w_dw3b, b_dw3b, w_out, b_out, out);
}